// round 7
// baseline (speedup 1.0000x reference)
#include <cuda_runtime.h>

// BranchRoute: score = sigmoid(x @ gate_w + gate_b); mask_i = score_i > 0.5
// out = concat(x*m0, x*m1, x*(m0+m1)), each [N, D] fp32.
// sigmoid(z) > 0.5 <=> z > 0, so only the dot-product sign matters.
//
// R7 = R1 (best: 86.5us, DRAM 73.2%) with exactly ONE change:
// grid = 444 = exactly the resident set (3 blocks/SM at 76 regs), removing
// the ~2.7 persistent-wave transitions of the 1184-block launch.
// Rationale: R2-R6 established DRAM is pinned at 70-73% regardless of
// occupancy / burst shape / cache policy / prefetch / TMA stores -> the
// 1:3 read:write HBM bus-turnaround mix is the ceiling; only scheduling
// overhead is left to harvest.

#define THREADS 256
#define DIM 4096

__global__ void __launch_bounds__(THREADS)
branch_route_kernel(const float* __restrict__ x,
                    const float* __restrict__ gw,   // [D, 2]
                    const float* __restrict__ gb,   // [2]
                    float* __restrict__ out,        // [3, N, D]
                    int N)
{
    const int t = threadIdx.x;

    // Each thread owns columns {c*1024 + t*4 + j : c in 0..3, j in 0..3}.
    // Load the matching gate_w pairs (w[:,0], w[:,1]) once per block.
    float2 w[16];
#pragma unroll
    for (int c = 0; c < 4; c++) {
#pragma unroll
        for (int j = 0; j < 4; j++) {
            int col = c * 1024 + t * 4 + j;
            w[c * 4 + j] = ((const float2*)gw)[col];
        }
    }
    const float b0 = gb[0];
    const float b1 = gb[1];

    __shared__ float2 red[2][8];   // [parity][warp] partial (s0, s1)

    float* __restrict__ o0 = out;
    float* __restrict__ o1 = out + (size_t)N * DIM;
    float* __restrict__ oc = out + (size_t)2 * N * DIM;

    int parity = 0;
    for (int row = blockIdx.x; row < N; row += gridDim.x, parity ^= 1) {
        const float4* xr = (const float4*)(x + (size_t)row * DIM);

        // Load the row chunk (coalesced float4), keep in registers.
        float4 v[4];
#pragma unroll
        for (int c = 0; c < 4; c++) v[c] = xr[c * 256 + t];

        // Partial dots for both gate columns.
        float s0 = 0.f, s1 = 0.f;
#pragma unroll
        for (int c = 0; c < 4; c++) {
            s0 = fmaf(v[c].x, w[c * 4 + 0].x, s0);
            s1 = fmaf(v[c].x, w[c * 4 + 0].y, s1);
            s0 = fmaf(v[c].y, w[c * 4 + 1].x, s0);
            s1 = fmaf(v[c].y, w[c * 4 + 1].y, s1);
            s0 = fmaf(v[c].z, w[c * 4 + 2].x, s0);
            s1 = fmaf(v[c].z, w[c * 4 + 2].y, s1);
            s0 = fmaf(v[c].w, w[c * 4 + 3].x, s0);
            s1 = fmaf(v[c].w, w[c * 4 + 3].y, s1);
        }

        // Warp butterfly reduce.
#pragma unroll
        for (int o = 16; o > 0; o >>= 1) {
            s0 += __shfl_xor_sync(0xffffffffu, s0, o);
            s1 += __shfl_xor_sync(0xffffffffu, s1, o);
        }
        if ((t & 31) == 0) red[parity][t >> 5] = make_float2(s0, s1);
        __syncthreads();   // single barrier per row (double-buffered shared)

        float d0 = b0, d1 = b1;
#pragma unroll
        for (int k = 0; k < 8; k++) {
            d0 += red[parity][k].x;
            d1 += red[parity][k].y;
        }

        const float f0 = d0 > 0.f ? 1.f : 0.f;
        const float f1 = d1 > 0.f ? 1.f : 0.f;
        const float fc = f0 + f1;

        const size_t base = (size_t)row * (DIM / 4);
        float4* __restrict__ p0 = (float4*)o0 + base;
        float4* __restrict__ p1 = (float4*)o1 + base;
        float4* __restrict__ pc = (float4*)oc + base;

#pragma unroll
        for (int c = 0; c < 4; c++) {
            const int idx = c * 256 + t;
            float4 a, b, s;
            a.x = f0 * v[c].x; a.y = f0 * v[c].y; a.z = f0 * v[c].z; a.w = f0 * v[c].w;
            b.x = f1 * v[c].x; b.y = f1 * v[c].y; b.z = f1 * v[c].z; b.w = f1 * v[c].w;
            s.x = fc * v[c].x; s.y = fc * v[c].y; s.z = fc * v[c].z; s.w = fc * v[c].w;
            p0[idx] = a;
            p1[idx] = b;
            pc[idx] = s;
        }
    }
}

extern "C" void kernel_launch(void* const* d_in, const int* in_sizes, int n_in,
                              void* d_out, int out_size)
{
    const float* x  = (const float*)d_in[0];
    const float* gw = (const float*)d_in[1];
    const float* gb = (const float*)d_in[2];
    float* out = (float*)d_out;

    const int N = in_sizes[0] / DIM;   // 8192

    // Exactly the resident set: 3 blocks/SM at 76 regs -> 148*3 = 444.
    const int grid = 148 * 3;
    branch_route_kernel<<<grid, THREADS>>>(x, gw, gb, out, N);
}

// round 8
// speedup vs baseline: 1.1147x; 1.1147x over previous
#include <cuda_runtime.h>

// BranchRoute: score = sigmoid(x @ gate_w + gate_b); mask_i = score_i > 0.5
// out = concat(x*m0, x*m1, x*(m0+m1)), each [N, D] fp32.
// sigmoid(z) > 0.5 <=> z > 0, so only the dot-product sign matters.
//
// R8: one row per block, grid = N = 8192 (max oversubscription).
// Evidence: grid 296 -> 85.6us, 444 -> 88.4us, 1184 -> 82.6us. Bigger grid
// wins because queued blocks refill SMs as others finish, hiding the ~2x
// per-CTA completion spread that a single-wave persistent launch exposes as
// an idle tail. gate_w (32KB) is L2-resident; per-block register loads of it
// cost L2 traffic only (no DRAM). No loop, no parity double-buffer.

#define THREADS 256
#define DIM 4096

__global__ void __launch_bounds__(THREADS)
branch_route_kernel(const float* __restrict__ x,
                    const float* __restrict__ gw,   // [D, 2]
                    const float* __restrict__ gb,   // [2]
                    float* __restrict__ out,        // [3, N, D]
                    int N)
{
    const int t = threadIdx.x;
    const int row = blockIdx.x;

    // This thread's 16 gate_w pairs (columns c*1024 + 4t + j), from L2.
    float2 w[16];
#pragma unroll
    for (int c = 0; c < 4; c++) {
#pragma unroll
        for (int j = 0; j < 4; j++) {
            int col = c * 1024 + t * 4 + j;
            w[c * 4 + j] = __ldg(&((const float2*)gw)[col]);
        }
    }

    // Load the row chunk (coalesced float4), keep in registers.
    const float4* xr = (const float4*)(x + (size_t)row * DIM);
    float4 v[4];
#pragma unroll
    for (int c = 0; c < 4; c++) v[c] = xr[c * 256 + t];

    // Partial dots for both gate columns.
    float s0 = 0.f, s1 = 0.f;
#pragma unroll
    for (int c = 0; c < 4; c++) {
        s0 = fmaf(v[c].x, w[c * 4 + 0].x, s0);
        s1 = fmaf(v[c].x, w[c * 4 + 0].y, s1);
        s0 = fmaf(v[c].y, w[c * 4 + 1].x, s0);
        s1 = fmaf(v[c].y, w[c * 4 + 1].y, s1);
        s0 = fmaf(v[c].z, w[c * 4 + 2].x, s0);
        s1 = fmaf(v[c].z, w[c * 4 + 2].y, s1);
        s0 = fmaf(v[c].w, w[c * 4 + 3].x, s0);
        s1 = fmaf(v[c].w, w[c * 4 + 3].y, s1);
    }

    // Warp butterfly reduce.
#pragma unroll
    for (int o = 16; o > 0; o >>= 1) {
        s0 += __shfl_xor_sync(0xffffffffu, s0, o);
        s1 += __shfl_xor_sync(0xffffffffu, s1, o);
    }

    __shared__ float2 red[8];
    if ((t & 31) == 0) red[t >> 5] = make_float2(s0, s1);
    __syncthreads();

    float d0 = gb[0], d1 = gb[1];
#pragma unroll
    for (int k = 0; k < 8; k++) {
        d0 += red[k].x;
        d1 += red[k].y;
    }

    const float f0 = d0 > 0.f ? 1.f : 0.f;
    const float f1 = d1 > 0.f ? 1.f : 0.f;
    const float fc = f0 + f1;

    const size_t base = (size_t)row * (DIM / 4);
    float4* __restrict__ p0 = (float4*)out + base;
    float4* __restrict__ p1 = (float4*)out + (size_t)N * (DIM / 4) + base;
    float4* __restrict__ pc = (float4*)out + (size_t)2 * N * (DIM / 4) + base;

#pragma unroll
    for (int c = 0; c < 4; c++) {
        const int idx = c * 256 + t;
        float4 a, b, s;
        a.x = f0 * v[c].x; a.y = f0 * v[c].y; a.z = f0 * v[c].z; a.w = f0 * v[c].w;
        b.x = f1 * v[c].x; b.y = f1 * v[c].y; b.z = f1 * v[c].z; b.w = f1 * v[c].w;
        s.x = fc * v[c].x; s.y = fc * v[c].y; s.z = fc * v[c].z; s.w = fc * v[c].w;
        p0[idx] = a;
        p1[idx] = b;
        pc[idx] = s;
    }
}

extern "C" void kernel_launch(void* const* d_in, const int* in_sizes, int n_in,
                              void* d_out, int out_size)
{
    const float* x  = (const float*)d_in[0];
    const float* gw = (const float*)d_in[1];
    const float* gb = (const float*)d_in[2];
    float* out = (float*)d_out;

    const int N = in_sizes[0] / DIM;   // 8192

    // One row per block: maximum scheduling granularity.
    branch_route_kernel<<<N, THREADS>>>(x, gw, gb, out, N);
}